// round 1
// baseline (speedup 1.0000x reference)
#include <cuda_runtime.h>
#include <math.h>

#define NN   100000
#define FN   2
#define FE   7
#define NH   4
#define HC   32
#define EMAX 3200000
#define EFMAX (EMAX + NN)
#define REGF 500

// ---------------- scratch (static device globals; no runtime alloc) ----------------
__device__ float g_xl[(size_t)NN * HC];
__device__ float g_xr[(size_t)NN * HC];
__device__ float g_ex[(size_t)EFMAX * NH];   // logits, then overwritten with exp()
__device__ float g_mx[(size_t)NN * NH];
__device__ float g_den[(size_t)NN * NH];
__device__ float g_h1[(size_t)NN * HC];
__device__ float g_h2[(size_t)NN * HC];
__device__ float g_eamean[FE];               // raw sums; scaled by 1/E at use site
__device__ float g_stats[2 * HC];            // BN sums / sumsq
__device__ float g_ab[2 * HC];               // BN affine: A=scale, B=shift
__device__ float g_weff[HC + 1];             // collapsed Wreg@Wend (+ effective bias)

__device__ __forceinline__ float lrelu(float x, float s) { return x > 0.f ? x : s * x; }

__device__ __forceinline__ void atomicMaxF(float* addr, float v) {
    if (v >= 0.f) atomicMax((int*)addr, __float_as_int(v));
    else          atomicMin((unsigned int*)addr, __float_as_uint(v));
}

__device__ __forceinline__ void redAddV4(float* p, float4 v) {
    asm volatile("red.global.add.v4.f32 [%0], {%1,%2,%3,%4};"
                 :: "l"(p), "f"(v.x), "f"(v.y), "f"(v.z), "f"(v.w) : "memory");
}

// ---------------- small init / reduction kernels ----------------
__global__ void zero_ea_stats_kernel() {
    int t = threadIdx.x;
    if (t < FE) g_eamean[t] = 0.f;
    if (t < 2 * HC) g_stats[t] = 0.f;
}
__global__ void zero_stats_kernel() {
    if (threadIdx.x < 2 * HC) g_stats[threadIdx.x] = 0.f;
}

__global__ void ea_sum_kernel(const float* __restrict__ ea, int E) {
    float loc[FE];
#pragma unroll
    for (int k = 0; k < FE; k++) loc[k] = 0.f;
    int stride = gridDim.x * blockDim.x;
    for (int e = blockIdx.x * blockDim.x + threadIdx.x; e < E; e += stride) {
#pragma unroll
        for (int k = 0; k < FE; k++) loc[k] += ea[(size_t)e * FE + k];
    }
    __shared__ float sh[FE];
    if (threadIdx.x < FE) sh[threadIdx.x] = 0.f;
    __syncthreads();
#pragma unroll
    for (int k = 0; k < FE; k++) {
        float v = loc[k];
#pragma unroll
        for (int o = 16; o > 0; o >>= 1) v += __shfl_down_sync(0xffffffffu, v, o);
        if ((threadIdx.x & 31) == 0) atomicAdd(&sh[k], v);
    }
    __syncthreads();
    if (threadIdx.x < FE) atomicAdd(&g_eamean[threadIdx.x], sh[threadIdx.x]);
}

// weff[c] = sum_r Wreg[c,r]*Wend[r];  weff[HC] = breg@Wend + bend  (no activation between)
__global__ void weff_kernel(const float* __restrict__ Wreg, const float* __restrict__ breg,
                            const float* __restrict__ Wend, const float* __restrict__ bend) {
    int c = threadIdx.x;
    if (c < HC) {
        float s = 0.f;
        for (int r = 0; r < REGF; r++) s += Wreg[c * REGF + r] * Wend[r];
        g_weff[c] = s;
    } else if (c == HC) {
        float s = bend[0];
        for (int r = 0; r < REGF; r++) s += breg[r] * Wend[r];
        g_weff[HC] = s;
    }
}

// ---------------- node transform: xl = h@Wl+bl, xr = h@Wr+br; also seeds out/mx/den ----
template <int F, bool BN>
__global__ void transform_kernel(const float* __restrict__ xin, int insel, int osel,
                                 const float* __restrict__ Wl, const float* __restrict__ bl,
                                 const float* __restrict__ Wr, const float* __restrict__ br,
                                 const float* __restrict__ bout, int n) {
    __shared__ float sWl[F * HC], sWr[F * HC], sb[3 * HC];
    for (int t = threadIdx.x; t < F * HC; t += blockDim.x) { sWl[t] = Wl[t]; sWr[t] = Wr[t]; }
    for (int t = threadIdx.x; t < HC; t += blockDim.x) {
        sb[t] = bl[t]; sb[HC + t] = br[t]; sb[2 * HC + t] = bout[t];
    }
    __syncthreads();
    int i = blockIdx.x * blockDim.x + threadIdx.x;
    if (i >= n) return;
    const float* hin = (F == FN) ? xin : (insel ? g_h2 : g_h1);
    float* out = osel ? g_h2 : g_h1;

    float in[F];
#pragma unroll
    for (int k = 0; k < F; k++) {
        float v = hin[(size_t)i * F + k];
        if (BN) { v = v * g_ab[k] + g_ab[HC + k]; v = lrelu(v, 0.01f); }
        in[k] = v;
    }
    float vl[HC], vr[HC];
#pragma unroll
    for (int c = 0; c < HC; c++) { vl[c] = sb[c]; vr[c] = sb[HC + c]; }
#pragma unroll
    for (int k = 0; k < F; k++) {
        float a = in[k];
#pragma unroll
        for (int c = 0; c < HC; c++) { vl[c] += a * sWl[k * HC + c]; vr[c] += a * sWr[k * HC + c]; }
    }
    float4* pl = (float4*)(g_xl + (size_t)i * HC);
    float4* pr = (float4*)(g_xr + (size_t)i * HC);
    float4* po = (float4*)(out + (size_t)i * HC);
#pragma unroll
    for (int q = 0; q < 8; q++) {
        pl[q] = make_float4(vl[q * 4], vl[q * 4 + 1], vl[q * 4 + 2], vl[q * 4 + 3]);
        pr[q] = make_float4(vr[q * 4], vr[q * 4 + 1], vr[q * 4 + 2], vr[q * 4 + 3]);
        po[q] = make_float4(sb[2 * HC + q * 4], sb[2 * HC + q * 4 + 1],
                            sb[2 * HC + q * 4 + 2], sb[2 * HC + q * 4 + 3]);
    }
    *(float4*)(g_mx + (size_t)i * NH) = make_float4(-INFINITY, -INFINITY, -INFINITY, -INFINITY);
    *(float4*)(g_den + (size_t)i * NH) = make_float4(0.f, 0.f, 0.f, 0.f);
}

// ---------------- edge pass 1: logits + segment-max ----------------
__global__ void edge_logits_kernel(const int* __restrict__ eidx, const float* __restrict__ ea,
                                   const float* __restrict__ We, const float* __restrict__ att,
                                   int E, int n, float invE) {
    __shared__ float sWe[FE * HC];
    __shared__ float satt[HC];
    __shared__ float smn[FE];
    for (int t = threadIdx.x; t < FE * HC; t += blockDim.x) sWe[t] = We[t];
    if (threadIdx.x < HC) satt[threadIdx.x] = att[threadIdx.x];
    if (threadIdx.x < FE) smn[threadIdx.x] = g_eamean[threadIdx.x] * invE;
    __syncthreads();
    int e = blockIdx.x * blockDim.x + threadIdx.x;
    if (e >= E + n) return;

    int s, d;
    float eav[FE];
    if (e < E) {
        s = eidx[e]; d = eidx[E + e];
#pragma unroll
        for (int k = 0; k < FE; k++) eav[k] = ea[(size_t)e * FE + k];
    } else {
        s = d = e - E;
#pragma unroll
        for (int k = 0; k < FE; k++) eav[k] = smn[k];
    }

    float lg[NH] = {0.f, 0.f, 0.f, 0.f};
    const float4* xs = (const float4*)(g_xl + (size_t)s * HC);
    const float4* xd = (const float4*)(g_xr + (size_t)d * HC);
#pragma unroll
    for (int q = 0; q < 8; q++) {
        float4 a = xs[q];
        float4 b = xd[q];
        float vv[4] = {a.x + b.x, a.y + b.y, a.z + b.z, a.w + b.w};
#pragma unroll
        for (int j = 0; j < 4; j++) {
            int c = q * 4 + j;
            float m = vv[j];
#pragma unroll
            for (int k = 0; k < FE; k++) m += eav[k] * sWe[k * HC + c];
            m = lrelu(m, 0.2f);
            lg[q >> 1] += m * satt[c];
        }
    }
    ((float4*)g_ex)[e] = make_float4(lg[0], lg[1], lg[2], lg[3]);
#pragma unroll
    for (int h = 0; h < NH; h++) atomicMaxF(&g_mx[(size_t)d * NH + h], lg[h]);
}

// ---------------- edge pass 2: exp + segment-sum ----------------
__global__ void edge_exp_kernel(const int* __restrict__ eidx, int E, int n) {
    int e = blockIdx.x * blockDim.x + threadIdx.x;
    if (e >= E + n) return;
    int d = (e < E) ? eidx[E + e] : e - E;
    float4 lg = ((const float4*)g_ex)[e];
    float4 mx = *(const float4*)(g_mx + (size_t)d * NH);
    float4 ex = make_float4(expf(lg.x - mx.x), expf(lg.y - mx.y),
                            expf(lg.z - mx.z), expf(lg.w - mx.w));
    ((float4*)g_ex)[e] = ex;
    redAddV4(g_den + (size_t)d * NH, ex);
}

// ---------------- edge pass 3: normalize + scatter-add xl[src]*alpha to out[dst] --------
__global__ void edge_aggr_kernel(const int* __restrict__ eidx, int E, int n, int osel) {
    int e = blockIdx.x * blockDim.x + threadIdx.x;
    if (e >= E + n) return;
    int s, d;
    if (e < E) { s = eidx[e]; d = eidx[E + e]; }
    else       { s = d = e - E; }
    float4 ex = ((const float4*)g_ex)[e];
    float4 dn = *(const float4*)(g_den + (size_t)d * NH);
    float al[NH] = {ex.x / (dn.x + 1e-16f), ex.y / (dn.y + 1e-16f),
                    ex.z / (dn.z + 1e-16f), ex.w / (dn.w + 1e-16f)};
    const float4* xs = (const float4*)(g_xl + (size_t)s * HC);
    float* od = (osel ? g_h2 : g_h1) + (size_t)d * HC;
#pragma unroll
    for (int q = 0; q < 8; q++) {
        float4 v = xs[q];
        float a = al[q >> 1];
        v.x *= a; v.y *= a; v.z *= a; v.w *= a;
        redAddV4(od + q * 4, v);
    }
}

// ---------------- BatchNorm stats / finalize ----------------
__global__ void bn_stats_kernel(int sel, int n) {
    const float* h = sel ? g_h2 : g_h1;
    int c = threadIdx.x & (HC - 1);
    int g = threadIdx.x >> 5;  // warp id: one 32ch row per warp per iter
    int warps = blockDim.x >> 5;
    float s = 0.f, s2 = 0.f;
    for (int r = blockIdx.x * warps + g; r < n; r += gridDim.x * warps) {
        float v = h[(size_t)r * HC + c];
        s += v; s2 += v * v;
    }
    __shared__ float sh[2 * HC];
    if (threadIdx.x < 2 * HC) sh[threadIdx.x] = 0.f;
    __syncthreads();
    atomicAdd(&sh[c], s);
    atomicAdd(&sh[HC + c], s2);
    __syncthreads();
    if (threadIdx.x < 2 * HC) atomicAdd(&g_stats[threadIdx.x], sh[threadIdx.x]);
}

__global__ void bn_finalize_kernel(const float* __restrict__ gamma,
                                   const float* __restrict__ beta, float invn) {
    int c = threadIdx.x;
    if (c >= HC) return;
    float mu = g_stats[c] * invn;
    float var = g_stats[HC + c] * invn - mu * mu;
    float A = rsqrtf(var + 1e-5f) * gamma[c];
    g_ab[c] = A;
    g_ab[HC + c] = beta[c] - mu * A;
}

// ---------------- final head: out[i] = lrelu(h1[i]) . weff + beff ----------------
__global__ void final_kernel(float* __restrict__ out, int n) {
    __shared__ float sw[HC + 1];
    if (threadIdx.x < HC + 1) sw[threadIdx.x] = g_weff[threadIdx.x];
    __syncthreads();
    int i = blockIdx.x * blockDim.x + threadIdx.x;
    if (i >= n) return;
    const float4* hp = (const float4*)(g_h1 + (size_t)i * HC);
    float s = sw[HC];
#pragma unroll
    for (int q = 0; q < 8; q++) {
        float4 v = hp[q];
        s += lrelu(v.x, 0.01f) * sw[q * 4];
        s += lrelu(v.y, 0.01f) * sw[q * 4 + 1];
        s += lrelu(v.z, 0.01f) * sw[q * 4 + 2];
        s += lrelu(v.w, 0.01f) * sw[q * 4 + 3];
    }
    out[i] = s;
}

// ---------------- launch ----------------
extern "C" void kernel_launch(void* const* d_in, const int* in_sizes, int n_in,
                              void* d_out, int out_size) {
    const float* x    = (const float*)d_in[0];
    const int*   eidx = (const int*)d_in[1];
    const float* ea   = (const float*)d_in[2];
    const float* Wl1 = (const float*)d_in[3];  const float* bl1 = (const float*)d_in[4];
    const float* Wr1 = (const float*)d_in[5];  const float* br1 = (const float*)d_in[6];
    const float* We1 = (const float*)d_in[7];  const float* att1 = (const float*)d_in[8];
    const float* b1  = (const float*)d_in[9];
    const float* Wl2 = (const float*)d_in[10]; const float* bl2 = (const float*)d_in[11];
    const float* Wr2 = (const float*)d_in[12]; const float* br2 = (const float*)d_in[13];
    const float* We2 = (const float*)d_in[14]; const float* att2 = (const float*)d_in[15];
    const float* b2  = (const float*)d_in[16];
    const float* gamma = (const float*)d_in[17]; const float* beta = (const float*)d_in[18];
    const float* Wreg = (const float*)d_in[19];  const float* breg = (const float*)d_in[20];
    const float* Wend = (const float*)d_in[21];  const float* bend = (const float*)d_in[22];
    float* out = (float*)d_out;

    int n = in_sizes[0] / FN;
    int E = in_sizes[1] / 2;
    int ef = E + n;
    float invE = 1.f / (float)E;
    int nbN = (n + 255) / 256;
    int nbE = (ef + 255) / 256;

    zero_ea_stats_kernel<<<1, 64>>>();
    ea_sum_kernel<<<512, 256>>>(ea, E);
    weff_kernel<<<1, 64>>>(Wreg, breg, Wend, bend);

    // ---- layer 1 (F=2) ----
    transform_kernel<FN, false><<<nbN, 256>>>(x, 0, 0, Wl1, bl1, Wr1, br1, b1, n);
    edge_logits_kernel<<<nbE, 256>>>(eidx, ea, We1, att1, E, n, invE);
    edge_exp_kernel<<<nbE, 256>>>(eidx, E, n);
    edge_aggr_kernel<<<nbE, 256>>>(eidx, E, n, 0);   // -> g_h1

    // ---- BN1 + act fused into layer-2 transform ----
    bn_stats_kernel<<<256, 256>>>(0, n);
    bn_finalize_kernel<<<1, 32>>>(gamma, beta, 1.f / (float)n);

    // ---- layer 2 (F=32) ----
    transform_kernel<HC, true><<<nbN, 256>>>(x, 0, 1, Wl2, bl2, Wr2, br2, b2, n);
    edge_logits_kernel<<<nbE, 256>>>(eidx, ea, We2, att2, E, n, invE);
    edge_exp_kernel<<<nbE, 256>>>(eidx, E, n);
    edge_aggr_kernel<<<nbE, 256>>>(eidx, E, n, 1);   // -> g_h2

    // ---- BN2 ----
    zero_stats_kernel<<<1, 64>>>();
    bn_stats_kernel<<<256, 256>>>(1, n);
    bn_finalize_kernel<<<1, 32>>>(gamma, beta, 1.f / (float)n);

    // ---- layer 3 (F=32, same weights as layer 2) ----
    transform_kernel<HC, true><<<nbN, 256>>>(x, 1, 0, Wl2, bl2, Wr2, br2, b2, n);
    edge_logits_kernel<<<nbE, 256>>>(eidx, ea, We2, att2, E, n, invE);
    edge_exp_kernel<<<nbE, 256>>>(eidx, E, n);
    edge_aggr_kernel<<<nbE, 256>>>(eidx, E, n, 0);   // -> g_h1

    // ---- collapsed head: lrelu -> (Wreg@Wend) dot ----
    final_kernel<<<nbN, 256>>>(out, n);
}

// round 2
// speedup vs baseline: 1.3972x; 1.3972x over previous
#include <cuda_runtime.h>
#include <math.h>

#define NN   100000
#define FN   2
#define FE   7
#define NH   4
#define HC   32
#define REGF 500

// ---------------- scratch (static device globals; no runtime alloc) ----------------
__device__ float g_xl[(size_t)NN * HC];
__device__ float g_xr[(size_t)NN * HC];
__device__ float g_den[(size_t)NN * NH];
__device__ float g_h1[(size_t)NN * HC];     // also unnormalized accumulator
__device__ float g_h2[(size_t)NN * HC];
__device__ float g_eamean[FE];               // raw sums; scaled by 1/E at use site
__device__ float g_stats[2 * HC];            // BN sums / sumsq
__device__ float g_ab[2 * HC];               // BN affine: A=scale, B=shift
__device__ float g_weff[HC + 1];             // collapsed Wreg@Wend (+ effective bias)

__device__ __forceinline__ float lrelu(float x, float s) { return x > 0.f ? x : s * x; }

__device__ __forceinline__ void redAddV4(float* p, float4 v) {
    asm volatile("red.global.add.v4.f32 [%0], {%1,%2,%3,%4};"
                 :: "l"(p), "f"(v.x), "f"(v.y), "f"(v.z), "f"(v.w) : "memory");
}

// ---------------- small init / reduction kernels ----------------
__global__ void zero_ea_kernel() {
    int t = threadIdx.x;
    if (t < FE) g_eamean[t] = 0.f;
}

__global__ void ea_sum_kernel(const float* __restrict__ ea, int E) {
    float loc[FE];
#pragma unroll
    for (int k = 0; k < FE; k++) loc[k] = 0.f;
    int stride = gridDim.x * blockDim.x;
    for (int e = blockIdx.x * blockDim.x + threadIdx.x; e < E; e += stride) {
#pragma unroll
        for (int k = 0; k < FE; k++) loc[k] += ea[(size_t)e * FE + k];
    }
    __shared__ float sh[FE];
    if (threadIdx.x < FE) sh[threadIdx.x] = 0.f;
    __syncthreads();
#pragma unroll
    for (int k = 0; k < FE; k++) {
        float v = loc[k];
#pragma unroll
        for (int o = 16; o > 0; o >>= 1) v += __shfl_down_sync(0xffffffffu, v, o);
        if ((threadIdx.x & 31) == 0) atomicAdd(&sh[k], v);
    }
    __syncthreads();
    if (threadIdx.x < FE) atomicAdd(&g_eamean[threadIdx.x], sh[threadIdx.x]);
}

// weff[c] = sum_r Wreg[c,r]*Wend[r];  weff[HC] = breg@Wend + bend  (no activation between)
__global__ void weff_kernel(const float* __restrict__ Wreg, const float* __restrict__ breg,
                            const float* __restrict__ Wend, const float* __restrict__ bend) {
    int c = threadIdx.x;
    if (c < HC) {
        float s = 0.f;
        for (int r = 0; r < REGF; r++) s += Wreg[c * REGF + r] * Wend[r];
        g_weff[c] = s;
    } else if (c == HC) {
        float s = bend[0];
        for (int r = 0; r < REGF; r++) s += breg[r] * Wend[r];
        g_weff[HC] = s;
    }
}

// ---- node transform: xl = h@Wl+bl, xr = h@Wr+br; seeds acc=0, den=0; zeros BN stats ----
template <int F, bool BN>
__global__ void transform_kernel(const float* __restrict__ xin, int insel, int osel,
                                 const float* __restrict__ Wl, const float* __restrict__ bl,
                                 const float* __restrict__ Wr, const float* __restrict__ br,
                                 int n) {
    __shared__ float sWl[F * HC], sWr[F * HC], sb[2 * HC];
    for (int t = threadIdx.x; t < F * HC; t += blockDim.x) { sWl[t] = Wl[t]; sWr[t] = Wr[t]; }
    for (int t = threadIdx.x; t < HC; t += blockDim.x) { sb[t] = bl[t]; sb[HC + t] = br[t]; }
    if (blockIdx.x == 0 && threadIdx.x < 2 * HC) g_stats[threadIdx.x] = 0.f;
    __syncthreads();
    int i = blockIdx.x * blockDim.x + threadIdx.x;
    if (i >= n) return;
    const float* hin = (F == FN) ? xin : (insel ? g_h2 : g_h1);
    float* acc = osel ? g_h2 : g_h1;

    float in[F];
#pragma unroll
    for (int k = 0; k < F; k++) {
        float v = hin[(size_t)i * F + k];
        if (BN) { v = v * g_ab[k] + g_ab[HC + k]; v = lrelu(v, 0.01f); }
        in[k] = v;
    }
    float vl[HC], vr[HC];
#pragma unroll
    for (int c = 0; c < HC; c++) { vl[c] = sb[c]; vr[c] = sb[HC + c]; }
#pragma unroll
    for (int k = 0; k < F; k++) {
        float a = in[k];
#pragma unroll
        for (int c = 0; c < HC; c++) { vl[c] += a * sWl[k * HC + c]; vr[c] += a * sWr[k * HC + c]; }
    }
    float4* pl = (float4*)(g_xl + (size_t)i * HC);
    float4* pr = (float4*)(g_xr + (size_t)i * HC);
    float4* pa = (float4*)(acc + (size_t)i * HC);
    float4 z = make_float4(0.f, 0.f, 0.f, 0.f);
#pragma unroll
    for (int q = 0; q < 8; q++) {
        pl[q] = make_float4(vl[q * 4], vl[q * 4 + 1], vl[q * 4 + 2], vl[q * 4 + 3]);
        pr[q] = make_float4(vr[q * 4], vr[q * 4 + 1], vr[q * 4 + 2], vr[q * 4 + 3]);
        pa[q] = z;
    }
    *(float4*)(g_den + (size_t)i * NH) = z;
}

// ------- single fused edge pass: logits -> exp -> red.add den[dst] and acc[dst] --------
__global__ void edge_fused_kernel(const int* __restrict__ eidx, const float* __restrict__ ea,
                                  const float* __restrict__ We, const float* __restrict__ att,
                                  int E, int n, float invE, int osel) {
    __shared__ float sWe[FE * HC];
    __shared__ float satt[HC];
    __shared__ float smn[FE];
    for (int t = threadIdx.x; t < FE * HC; t += blockDim.x) sWe[t] = We[t];
    if (threadIdx.x < HC) satt[threadIdx.x] = att[threadIdx.x];
    if (threadIdx.x < FE) smn[threadIdx.x] = g_eamean[threadIdx.x] * invE;
    __syncthreads();
    int e = blockIdx.x * blockDim.x + threadIdx.x;
    if (e >= E + n) return;

    int s, d;
    float eav[FE];
    if (e < E) {
        s = eidx[e]; d = eidx[E + e];
#pragma unroll
        for (int k = 0; k < FE; k++) eav[k] = ea[(size_t)e * FE + k];
    } else {
        s = d = e - E;
#pragma unroll
        for (int k = 0; k < FE; k++) eav[k] = smn[k];
    }

    float lg[NH] = {0.f, 0.f, 0.f, 0.f};
    float4 xs4[8];
    const float4* xs = (const float4*)(g_xl + (size_t)s * HC);
    const float4* xd = (const float4*)(g_xr + (size_t)d * HC);
#pragma unroll
    for (int q = 0; q < 8; q++) {
        float4 a = xs[q];
        xs4[q] = a;
        float4 b = xd[q];
        float vv[4] = {a.x + b.x, a.y + b.y, a.z + b.z, a.w + b.w};
#pragma unroll
        for (int j = 0; j < 4; j++) {
            int c = q * 4 + j;
            float m = vv[j];
#pragma unroll
            for (int k = 0; k < FE; k++) m += eav[k] * sWe[k * HC + c];
            m = lrelu(m, 0.2f);
            lg[q >> 1] += m * satt[c];
        }
    }
    float exh[NH];
#pragma unroll
    for (int h = 0; h < NH; h++) exh[h] = __expf(lg[h]);

    redAddV4(g_den + (size_t)d * NH, make_float4(exh[0], exh[1], exh[2], exh[3]));
    float* od = (osel ? g_h2 : g_h1) + (size_t)d * HC;
#pragma unroll
    for (int q = 0; q < 8; q++) {
        float a = exh[q >> 1];
        float4 v = xs4[q];
        v.x *= a; v.y *= a; v.z *= a; v.w *= a;
        redAddV4(od + q * 4, v);
    }
}

// -------- finalize h = acc/den + bias, write h, accumulate BN stats (warp-per-row) ------
__global__ void fin_stats_kernel(int sel, const float* __restrict__ bias, int n) {
    float* h = sel ? g_h2 : g_h1;
    int c = threadIdx.x & (HC - 1);
    int g = threadIdx.x >> 5;
    int warps = blockDim.x >> 5;
    float b = bias[c];
    float s = 0.f, s2 = 0.f;
    for (int r = blockIdx.x * warps + g; r < n; r += gridDim.x * warps) {
        float acc = h[(size_t)r * HC + c];
        float den = g_den[(size_t)r * NH + (c >> 3)];
        float v = acc / (den + 1e-16f) + b;
        h[(size_t)r * HC + c] = v;
        s += v; s2 += v * v;
    }
    __shared__ float sh[2 * HC];
    if (threadIdx.x < 2 * HC) sh[threadIdx.x] = 0.f;
    __syncthreads();
    atomicAdd(&sh[c], s);
    atomicAdd(&sh[HC + c], s2);
    __syncthreads();
    if (threadIdx.x < 2 * HC) atomicAdd(&g_stats[threadIdx.x], sh[threadIdx.x]);
}

__global__ void bn_finalize_kernel(const float* __restrict__ gamma,
                                   const float* __restrict__ beta, float invn) {
    int c = threadIdx.x;
    if (c >= HC) return;
    float mu = g_stats[c] * invn;
    float var = g_stats[HC + c] * invn - mu * mu;
    float A = rsqrtf(var + 1e-5f) * gamma[c];
    g_ab[c] = A;
    g_ab[HC + c] = beta[c] - mu * A;
}

// ---- final head: h = acc/den + b2 ; out[i] = lrelu(h) . weff + beff ----
__global__ void fin_head_kernel(const float* __restrict__ bias, float* __restrict__ out, int n) {
    __shared__ float sw[HC + 1];
    __shared__ float sb[HC];
    if (threadIdx.x < HC + 1) sw[threadIdx.x] = g_weff[threadIdx.x];
    if (threadIdx.x < HC) sb[threadIdx.x] = bias[threadIdx.x];
    __syncthreads();
    int i = blockIdx.x * blockDim.x + threadIdx.x;
    if (i >= n) return;
    const float4* hp = (const float4*)(g_h1 + (size_t)i * HC);
    float4 dn = *(const float4*)(g_den + (size_t)i * NH);
    float den[NH] = {dn.x + 1e-16f, dn.y + 1e-16f, dn.z + 1e-16f, dn.w + 1e-16f};
    float s = sw[HC];
#pragma unroll
    for (int q = 0; q < 8; q++) {
        float4 v = hp[q];
        float d = den[q >> 1];
        float h0 = v.x / d + sb[q * 4];
        float h1 = v.y / d + sb[q * 4 + 1];
        float h2 = v.z / d + sb[q * 4 + 2];
        float h3 = v.w / d + sb[q * 4 + 3];
        s += lrelu(h0, 0.01f) * sw[q * 4];
        s += lrelu(h1, 0.01f) * sw[q * 4 + 1];
        s += lrelu(h2, 0.01f) * sw[q * 4 + 2];
        s += lrelu(h3, 0.01f) * sw[q * 4 + 3];
    }
    out[i] = s;
}

// ---------------- launch ----------------
extern "C" void kernel_launch(void* const* d_in, const int* in_sizes, int n_in,
                              void* d_out, int out_size) {
    const float* x    = (const float*)d_in[0];
    const int*   eidx = (const int*)d_in[1];
    const float* ea   = (const float*)d_in[2];
    const float* Wl1 = (const float*)d_in[3];  const float* bl1 = (const float*)d_in[4];
    const float* Wr1 = (const float*)d_in[5];  const float* br1 = (const float*)d_in[6];
    const float* We1 = (const float*)d_in[7];  const float* att1 = (const float*)d_in[8];
    const float* b1  = (const float*)d_in[9];
    const float* Wl2 = (const float*)d_in[10]; const float* bl2 = (const float*)d_in[11];
    const float* Wr2 = (const float*)d_in[12]; const float* br2 = (const float*)d_in[13];
    const float* We2 = (const float*)d_in[14]; const float* att2 = (const float*)d_in[15];
    const float* b2  = (const float*)d_in[16];
    const float* gamma = (const float*)d_in[17]; const float* beta = (const float*)d_in[18];
    const float* Wreg = (const float*)d_in[19];  const float* breg = (const float*)d_in[20];
    const float* Wend = (const float*)d_in[21];  const float* bend = (const float*)d_in[22];
    float* out = (float*)d_out;

    int n = in_sizes[0] / FN;
    int E = in_sizes[1] / 2;
    int ef = E + n;
    float invE = 1.f / (float)E;
    int nbN = (n + 255) / 256;
    int nbE = (ef + 255) / 256;

    zero_ea_kernel<<<1, 32>>>();
    ea_sum_kernel<<<512, 256>>>(ea, E);
    weff_kernel<<<1, 64>>>(Wreg, breg, Wend, bend);

    // ---- layer 1 (F=2) ----
    transform_kernel<FN, false><<<nbN, 256>>>(x, 0, 0, Wl1, bl1, Wr1, br1, n);
    edge_fused_kernel<<<nbE, 256>>>(eidx, ea, We1, att1, E, n, invE, 0);   // -> g_h1 (raw)
    fin_stats_kernel<<<256, 256>>>(0, b1, n);                              // h1 final + BN stats
    bn_finalize_kernel<<<1, 32>>>(gamma, beta, 1.f / (float)n);

    // ---- layer 2 (F=32, BN+act fused into transform) ----
    transform_kernel<HC, true><<<nbN, 256>>>(x, 0, 1, Wl2, bl2, Wr2, br2, n);
    edge_fused_kernel<<<nbE, 256>>>(eidx, ea, We2, att2, E, n, invE, 1);   // -> g_h2 (raw)
    fin_stats_kernel<<<256, 256>>>(1, b2, n);
    bn_finalize_kernel<<<1, 32>>>(gamma, beta, 1.f / (float)n);

    // ---- layer 3 (F=32, same weights as layer 2) ----
    transform_kernel<HC, true><<<nbN, 256>>>(x, 1, 0, Wl2, bl2, Wr2, br2, n);
    edge_fused_kernel<<<nbE, 256>>>(eidx, ea, We2, att2, E, n, invE, 0);   // -> g_h1 (raw)

    // ---- collapsed head: normalize + bias + lrelu + (Wreg@Wend) dot ----
    fin_head_kernel<<<nbN, 256>>>(b2, out, n);
}

// round 3
// speedup vs baseline: 1.6161x; 1.1566x over previous
#include <cuda_runtime.h>
#include <math.h>

#define NN   100000
#define FN   2
#define FE   7
#define NH   4
#define HC   32
#define EMAX 3200000
#define REGF 500

// ---------------- scratch (static device globals; no runtime alloc) ----------------
__device__ float g_xl[(size_t)NN * HC];
__device__ float g_xr[(size_t)NN * HC];
__device__ float g_h1[(size_t)NN * HC];
__device__ float g_h2[(size_t)NN * HC];
__device__ int   g_cnt[NN];        // in-degree histogram
__device__ int   g_rowptr[NN + 1];
__device__ int   g_cur[NN];        // scatter cursor
__device__ int   g_psrc[EMAX];     // CSR-permuted src node ids
__device__ float g_pea[(size_t)EMAX * FE];  // CSR-permuted edge attrs
__device__ float g_eamean[FE];     // raw sums; scaled by 1/E at use site
__device__ float g_stats[2 * HC];  // BN sums / sumsq
__device__ float g_ab[2 * HC];     // BN affine: A=scale, B=shift
__device__ float g_weff[HC + 1];   // collapsed Wreg@Wend (+ effective bias)

__device__ __forceinline__ float lrelu(float x, float s) { return x > 0.f ? x : s * x; }

// ---------------- small init / reduction kernels ----------------
__global__ void zero_small_kernel() {
    int t = threadIdx.x;
    if (t < FE) g_eamean[t] = 0.f;
}
__global__ void zero_cnt_kernel(int n) {
    int i = blockIdx.x * blockDim.x + threadIdx.x;
    if (i < n) g_cnt[i] = 0;
}

__global__ void ea_sum_kernel(const float* __restrict__ ea, int E) {
    float loc[FE];
#pragma unroll
    for (int k = 0; k < FE; k++) loc[k] = 0.f;
    int stride = gridDim.x * blockDim.x;
    for (int e = blockIdx.x * blockDim.x + threadIdx.x; e < E; e += stride) {
#pragma unroll
        for (int k = 0; k < FE; k++) loc[k] += ea[(size_t)e * FE + k];
    }
    __shared__ float sh[FE];
    if (threadIdx.x < FE) sh[threadIdx.x] = 0.f;
    __syncthreads();
#pragma unroll
    for (int k = 0; k < FE; k++) {
        float v = loc[k];
#pragma unroll
        for (int o = 16; o > 0; o >>= 1) v += __shfl_down_sync(0xffffffffu, v, o);
        if ((threadIdx.x & 31) == 0) atomicAdd(&sh[k], v);
    }
    __syncthreads();
    if (threadIdx.x < FE) atomicAdd(&g_eamean[threadIdx.x], sh[threadIdx.x]);
}

__global__ void weff_kernel(const float* __restrict__ Wreg, const float* __restrict__ breg,
                            const float* __restrict__ Wend, const float* __restrict__ bend) {
    int c = threadIdx.x;
    if (c < HC) {
        float s = 0.f;
        for (int r = 0; r < REGF; r++) s += Wreg[c * REGF + r] * Wend[r];
        g_weff[c] = s;
    } else if (c == HC) {
        float s = bend[0];
        for (int r = 0; r < REGF; r++) s += breg[r] * Wend[r];
        g_weff[HC] = s;
    }
}

// ---------------- CSR build ----------------
__global__ void hist_kernel(const int* __restrict__ eidx, int E) {
    int e = blockIdx.x * blockDim.x + threadIdx.x;
    if (e < E) atomicAdd(&g_cnt[eidx[E + e]], 1);
}

__global__ void scan_kernel(int n) {
    __shared__ int a[1024];
    int t = threadIdx.x;
    int chunk = (n + 1023) / 1024;
    int lo = t * chunk;
    int hi = lo + chunk; if (hi > n) hi = n; if (lo > n) lo = n;
    int s = 0;
    for (int i = lo; i < hi; i++) s += g_cnt[i];
    a[t] = s;
    __syncthreads();
    for (int off = 1; off < 1024; off <<= 1) {
        int u = (t >= off) ? a[t - off] : 0;
        __syncthreads();
        a[t] += u;
        __syncthreads();
    }
    int run = a[t] - s;  // exclusive prefix for this chunk
    for (int i = lo; i < hi; i++) {
        int c = g_cnt[i];
        g_rowptr[i] = run;
        g_cur[i] = run;
        run += c;
    }
    if (t == 1023) g_rowptr[n] = a[1023];
}

__global__ void scatter_kernel(const int* __restrict__ eidx, const float* __restrict__ ea, int E) {
    int e = blockIdx.x * blockDim.x + threadIdx.x;
    if (e >= E) return;
    int s = eidx[e];
    int d = eidx[E + e];
    int pos = atomicAdd(&g_cur[d], 1);
    g_psrc[pos] = s;
#pragma unroll
    for (int k = 0; k < FE; k++) g_pea[(size_t)pos * FE + k] = ea[(size_t)e * FE + k];
}

// ---- node transform: xl = h@Wl+bl, xr = h@Wr+br; zeros BN stats (block 0) ----
template <int F, bool BN>
__global__ void transform_kernel(const float* __restrict__ xin, int insel,
                                 const float* __restrict__ Wl, const float* __restrict__ bl,
                                 const float* __restrict__ Wr, const float* __restrict__ br,
                                 int n) {
    __shared__ float sWl[F * HC], sWr[F * HC], sb[2 * HC];
    for (int t = threadIdx.x; t < F * HC; t += blockDim.x) { sWl[t] = Wl[t]; sWr[t] = Wr[t]; }
    for (int t = threadIdx.x; t < HC; t += blockDim.x) { sb[t] = bl[t]; sb[HC + t] = br[t]; }
    if (blockIdx.x == 0 && threadIdx.x < 2 * HC) g_stats[threadIdx.x] = 0.f;
    __syncthreads();
    int i = blockIdx.x * blockDim.x + threadIdx.x;
    if (i >= n) return;
    const float* hin = (F == FN) ? xin : (insel ? g_h2 : g_h1);

    float in[F];
#pragma unroll
    for (int k = 0; k < F; k++) {
        float v = hin[(size_t)i * F + k];
        if (BN) { v = v * g_ab[k] + g_ab[HC + k]; v = lrelu(v, 0.01f); }
        in[k] = v;
    }
    float vl[HC], vr[HC];
#pragma unroll
    for (int c = 0; c < HC; c++) { vl[c] = sb[c]; vr[c] = sb[HC + c]; }
#pragma unroll
    for (int k = 0; k < F; k++) {
        float a = in[k];
#pragma unroll
        for (int c = 0; c < HC; c++) { vl[c] += a * sWl[k * HC + c]; vr[c] += a * sWr[k * HC + c]; }
    }
    float4* pl = (float4*)(g_xl + (size_t)i * HC);
    float4* pr = (float4*)(g_xr + (size_t)i * HC);
#pragma unroll
    for (int q = 0; q < 8; q++) {
        pl[q] = make_float4(vl[q * 4], vl[q * 4 + 1], vl[q * 4 + 2], vl[q * 4 + 3]);
        pr[q] = make_float4(vr[q * 4], vr[q * 4 + 1], vr[q * 4 + 2], vr[q * 4 + 3]);
    }
}

// ---------------- warp-per-node GATv2 aggregation (no atomics in hot path) -------------
// lane layout: group g = lane>>3 handles edge slot (4 edges/iter);
//              cs = lane&7 owns channels [cs*4, cs*4+4)
// MODE 0: write h (+bias, normalized) and accumulate BN stats
// MODE 1: fuse collapsed regression head, write out[i] directly
template <int MODE>
__global__ void gat_aggr_kernel(const float* __restrict__ We, const float* __restrict__ att,
                                const float* __restrict__ bias, float invE, int n, int hsel,
                                float* __restrict__ out) {
    __shared__ float sWe[FE * HC];
    __shared__ float satt[HC];
    __shared__ float smn[8];
    __shared__ float sb[HC];
    __shared__ float swf[HC + 1];
    __shared__ float sst[2 * HC];
    int t = threadIdx.x;
    if (t < FE * HC) sWe[t] = We[t];
    if (t < HC) { satt[t] = att[t]; sb[t] = bias[t]; }
    if (t < FE) smn[t] = g_eamean[t] * invE;
    if (t == FE) smn[FE] = 0.f;
    if (MODE == 0 && t < 2 * HC) sst[t] = 0.f;
    if (MODE == 1 && t < HC + 1) swf[t] = g_weff[t];
    __syncthreads();

    int lane = threadIdx.x & 31;
    int g = lane >> 3, cs = lane & 7;
    int i = (blockIdx.x * blockDim.x + threadIdx.x) >> 5;
    if (i < n) {
        int r0 = g_rowptr[i];
        int deg = g_rowptr[i + 1] - r0;
        int total = deg + 1;  // + virtual self-loop (ea = mean)
        float4 xr4 = *(const float4*)(g_xr + (size_t)i * HC + cs * 4);
        float4 att4 = *(const float4*)(satt + cs * 4);
        float4 acc = make_float4(0.f, 0.f, 0.f, 0.f);
        float den = 0.f;

        for (int base = 0; base < total; base += 4) {
            int idx = base + g;
            bool valid = idx < total;
            int s = i;
            float eam;
            if (valid && idx < deg) {
                int p = r0 + idx;
                s = g_psrc[p];
                eam = (cs < FE) ? g_pea[(size_t)p * FE + cs] : 0.f;
            } else {
                eam = smn[cs];
            }
            float eav[FE];
#pragma unroll
            for (int k = 0; k < FE; k++)
                eav[k] = __shfl_sync(0xffffffffu, eam, g * 8 + k);

            float4 xl4 = *(const float4*)(g_xl + (size_t)s * HC + cs * 4);
            float e0 = 0.f, e1 = 0.f, e2 = 0.f, e3 = 0.f;
#pragma unroll
            for (int k = 0; k < FE; k++) {
                const float* w = sWe + k * HC + cs * 4;
                float a = eav[k];
                e0 += a * w[0]; e1 += a * w[1]; e2 += a * w[2]; e3 += a * w[3];
            }
            float m0 = lrelu(xl4.x + xr4.x + e0, 0.2f);
            float m1 = lrelu(xl4.y + xr4.y + e1, 0.2f);
            float m2 = lrelu(xl4.z + xr4.z + e2, 0.2f);
            float m3 = lrelu(xl4.w + xr4.w + e3, 0.2f);
            float pl = m0 * att4.x + m1 * att4.y + m2 * att4.z + m3 * att4.w;
            float lg = pl + __shfl_xor_sync(0xffffffffu, pl, 1);  // head logit
            float ex = valid ? __expf(lg) : 0.f;
            den += ex;
            acc.x += ex * xl4.x; acc.y += ex * xl4.y;
            acc.z += ex * xl4.z; acc.w += ex * xl4.w;
        }
        // reduce across the 4 edge groups (channel identity preserved)
#pragma unroll
        for (int off = 8; off < 32; off <<= 1) {
            acc.x += __shfl_xor_sync(0xffffffffu, acc.x, off);
            acc.y += __shfl_xor_sync(0xffffffffu, acc.y, off);
            acc.z += __shfl_xor_sync(0xffffffffu, acc.z, off);
            acc.w += __shfl_xor_sync(0xffffffffu, acc.w, off);
            den   += __shfl_xor_sync(0xffffffffu, den,   off);
        }
        if (g == 0) {
            float inv = 1.f / (den + 1e-16f);
            float h0 = acc.x * inv + sb[cs * 4];
            float h1 = acc.y * inv + sb[cs * 4 + 1];
            float h2 = acc.z * inv + sb[cs * 4 + 2];
            float h3 = acc.w * inv + sb[cs * 4 + 3];
            if (MODE == 0) {
                float* hp = (hsel ? g_h2 : g_h1) + (size_t)i * HC + cs * 4;
                *(float4*)hp = make_float4(h0, h1, h2, h3);
                atomicAdd(&sst[cs * 4 + 0], h0);
                atomicAdd(&sst[cs * 4 + 1], h1);
                atomicAdd(&sst[cs * 4 + 2], h2);
                atomicAdd(&sst[cs * 4 + 3], h3);
                atomicAdd(&sst[HC + cs * 4 + 0], h0 * h0);
                atomicAdd(&sst[HC + cs * 4 + 1], h1 * h1);
                atomicAdd(&sst[HC + cs * 4 + 2], h2 * h2);
                atomicAdd(&sst[HC + cs * 4 + 3], h3 * h3);
            } else {
                float s = lrelu(h0, 0.01f) * swf[cs * 4]
                        + lrelu(h1, 0.01f) * swf[cs * 4 + 1]
                        + lrelu(h2, 0.01f) * swf[cs * 4 + 2]
                        + lrelu(h3, 0.01f) * swf[cs * 4 + 3];
                s += __shfl_xor_sync(0x000000ffu, s, 1);
                s += __shfl_xor_sync(0x000000ffu, s, 2);
                s += __shfl_xor_sync(0x000000ffu, s, 4);
                if (cs == 0) out[i] = s + swf[HC];
            }
        }
    }
    if (MODE == 0) {
        __syncthreads();
        if (t < 2 * HC) atomicAdd(&g_stats[t], sst[t]);
    }
}

__global__ void bn_finalize_kernel(const float* __restrict__ gamma,
                                   const float* __restrict__ beta, float invn) {
    int c = threadIdx.x;
    if (c >= HC) return;
    float mu = g_stats[c] * invn;
    float var = g_stats[HC + c] * invn - mu * mu;
    float A = rsqrtf(var + 1e-5f) * gamma[c];
    g_ab[c] = A;
    g_ab[HC + c] = beta[c] - mu * A;
}

// ---------------- launch ----------------
extern "C" void kernel_launch(void* const* d_in, const int* in_sizes, int n_in,
                              void* d_out, int out_size) {
    const float* x    = (const float*)d_in[0];
    const int*   eidx = (const int*)d_in[1];
    const float* ea   = (const float*)d_in[2];
    const float* Wl1 = (const float*)d_in[3];  const float* bl1 = (const float*)d_in[4];
    const float* Wr1 = (const float*)d_in[5];  const float* br1 = (const float*)d_in[6];
    const float* We1 = (const float*)d_in[7];  const float* att1 = (const float*)d_in[8];
    const float* b1  = (const float*)d_in[9];
    const float* Wl2 = (const float*)d_in[10]; const float* bl2 = (const float*)d_in[11];
    const float* Wr2 = (const float*)d_in[12]; const float* br2 = (const float*)d_in[13];
    const float* We2 = (const float*)d_in[14]; const float* att2 = (const float*)d_in[15];
    const float* b2  = (const float*)d_in[16];
    const float* gamma = (const float*)d_in[17]; const float* beta = (const float*)d_in[18];
    const float* Wreg = (const float*)d_in[19];  const float* breg = (const float*)d_in[20];
    const float* Wend = (const float*)d_in[21];  const float* bend = (const float*)d_in[22];
    float* out = (float*)d_out;

    int n = in_sizes[0] / FN;
    int E = in_sizes[1] / 2;
    float invE = 1.f / (float)E;
    int nbN = (n + 255) / 256;
    int nbE = (E + 255) / 256;
    int nbW = (n * 32 + 255) / 256;  // warp-per-node grid

    // ---- one-time prep: edge-attr mean, collapsed head, CSR build ----
    zero_small_kernel<<<1, 32>>>();
    zero_cnt_kernel<<<nbN, 256>>>(n);
    ea_sum_kernel<<<512, 256>>>(ea, E);
    weff_kernel<<<1, 64>>>(Wreg, breg, Wend, bend);
    hist_kernel<<<nbE, 256>>>(eidx, E);
    scan_kernel<<<1, 1024>>>(n);
    scatter_kernel<<<nbE, 256>>>(eidx, ea, E);

    // ---- layer 1 (F=2) ----
    transform_kernel<FN, false><<<nbN, 256>>>(x, 0, Wl1, bl1, Wr1, br1, n);
    gat_aggr_kernel<0><<<nbW, 256>>>(We1, att1, b1, invE, n, 0, nullptr);  // -> g_h1 + stats
    bn_finalize_kernel<<<1, 32>>>(gamma, beta, 1.f / (float)n);

    // ---- layer 2 (F=32, BN+act fused into transform) ----
    transform_kernel<HC, true><<<nbN, 256>>>(x, 0, Wl2, bl2, Wr2, br2, n);
    gat_aggr_kernel<0><<<nbW, 256>>>(We2, att2, b2, invE, n, 1, nullptr);  // -> g_h2 + stats
    bn_finalize_kernel<<<1, 32>>>(gamma, beta, 1.f / (float)n);

    // ---- layer 3 (F=32, same weights; head fused) ----
    transform_kernel<HC, true><<<nbN, 256>>>(x, 1, Wl2, bl2, Wr2, br2, n);
    gat_aggr_kernel<1><<<nbW, 256>>>(We2, att2, b2, invE, n, 0, out);      // -> out
}